// round 16
// baseline (speedup 1.0000x reference)
#include <cuda_runtime.h>
#include <cstdint>
#include <cstddef>

// ---------------- problem constants ----------------
#define EMB   768
#define HDIM  64
#define NHEAD 12
#define NB    16
#define NH    56
#define NW    56
#define NTOK  (NB*NH*NW)          // 50176
#define SCALING 0.125f            // 64^-0.5
#define WSZ   (EMB*EMB)

// ---------------- scratch (device globals; allocation-free) ----------------
__device__ float    g_q[(size_t)NTOK * EMB];
__device__ float    g_k[(size_t)NTOK * EMB];
__device__ float    g_v[(size_t)NTOK * EMB];
__device__ unsigned g_xt[(size_t)NTOK * EMB];   // tf32 operand (x, later attn-out)
__device__ unsigned g_wt[(size_t)4 * WSZ];      // tf32 weights Wq,Wk,Wv,Wo

// ---------------- tf32 helpers ----------------
__device__ __forceinline__ unsigned f2tf(float x) {
    unsigned r;
    asm("cvt.rna.tf32.f32 %0, %1;" : "=r"(r) : "f"(x));
    return r;
}

__device__ __forceinline__ void mma_tf32(float* d, const unsigned* a, const unsigned* b) {
    asm volatile(
        "mma.sync.aligned.m16n8k8.row.col.f32.tf32.tf32.f32 "
        "{%0,%1,%2,%3}, {%4,%5,%6,%7}, {%8,%9}, {%0,%1,%2,%3};\n"
        : "+f"(d[0]), "+f"(d[1]), "+f"(d[2]), "+f"(d[3])
        : "r"(a[0]), "r"(a[1]), "r"(a[2]), "r"(a[3]),
          "r"(b[0]), "r"(b[1]));
}

// ---------------- tf32 pre-convert pass ----------------
__global__ __launch_bounds__(256)
void conv_tf32(const float* __restrict__ in, unsigned* __restrict__ out, int n4)
{
    const int i = blockIdx.x * 256 + threadIdx.x;
    if (i < n4) {
        const float4 v = *(const float4*)(in + (size_t)i * 4);
        uint4 o;
        o.x = f2tf(v.x); o.y = f2tf(v.y); o.z = f2tf(v.z); o.w = f2tf(v.w);
        *(uint4*)(out + (size_t)i * 4) = o;
    }
}

// ---------------- GEMM v6 ----------------
// C[M,768] = (A_tf32 @ W_tf32^T + bias) * scale. Pre-converted operands.
// 256 threads = 8 warps as 2(M) x 4(N); warp tile 64x64 (mt=4 x nt=8):
// per kk8 step 16 LDS.64 feed 32 mma (128 B/mma, -33% vs v5).
// BM=128, BN=256, BK=16, double-buffered, chunk loop unrolled x2
// (all smem offsets immediate). Layout identical to v5: row-major
// [row][LDK=40], k-pair interleave (k,k+4 adjacent -> LDS.64) and
// per-row XOR swizzle (conflict-free STS.32 / LDS.64).
#define BM4 128
#define BN4 256
#define LDK 40
#define BOFF (128*LDK)
#define GEMM_SMEM ((128 + 256) * LDK * 4)   // 61440 bytes

#define STORE6(OFFc, va0, va1, v0, v1, v2, v3) do { \
    usm[stA + (OFFc) + jx[0]] = (va0).x; \
    usm[stA + (OFFc) + jx[1]] = (va0).y; \
    usm[stA + (OFFc) + jx[2]] = (va0).z; \
    usm[stA + (OFFc) + jx[3]] = (va0).w; \
    usm[64*LDK + stA + (OFFc) + jx[0]] = (va1).x; \
    usm[64*LDK + stA + (OFFc) + jx[1]] = (va1).y; \
    usm[64*LDK + stA + (OFFc) + jx[2]] = (va1).z; \
    usm[64*LDK + stA + (OFFc) + jx[3]] = (va1).w; \
    usm[BOFF + stA + (OFFc) + jx[0]] = (v0).x; \
    usm[BOFF + stA + (OFFc) + jx[1]] = (v0).y; \
    usm[BOFF + stA + (OFFc) + jx[2]] = (v0).z; \
    usm[BOFF + stA + (OFFc) + jx[3]] = (v0).w; \
    usm[BOFF + 64*LDK + stA + (OFFc) + jx[0]] = (v1).x; \
    usm[BOFF + 64*LDK + stA + (OFFc) + jx[1]] = (v1).y; \
    usm[BOFF + 64*LDK + stA + (OFFc) + jx[2]] = (v1).z; \
    usm[BOFF + 64*LDK + stA + (OFFc) + jx[3]] = (v1).w; \
    usm[BOFF + 128*LDK + stA + (OFFc) + jx[0]] = (v2).x; \
    usm[BOFF + 128*LDK + stA + (OFFc) + jx[1]] = (v2).y; \
    usm[BOFF + 128*LDK + stA + (OFFc) + jx[2]] = (v2).z; \
    usm[BOFF + 128*LDK + stA + (OFFc) + jx[3]] = (v2).w; \
    usm[BOFF + 192*LDK + stA + (OFFc) + jx[0]] = (v3).x; \
    usm[BOFF + 192*LDK + stA + (OFFc) + jx[1]] = (v3).y; \
    usm[BOFF + 192*LDK + stA + (OFFc) + jx[2]] = (v3).z; \
    usm[BOFF + 192*LDK + stA + (OFFc) + jx[3]] = (v3).w; \
} while (0)

#define GEMM_STEP(KOFFc) do { \
    _Pragma("unroll") \
    for (int kk8 = 0; kk8 < 2; ++kk8) { \
        const int koff = (KOFFc) + kk8 * 8; \
        unsigned af[4][4]; \
        _Pragma("unroll") \
        for (int mt = 0; mt < 4; ++mt) { \
            const uint2 lo = *(const uint2*)&usm[fA + mt * (16 * LDK) + koff]; \
            const uint2 hi = *(const uint2*)&usm[fA + mt * (16 * LDK) + 8 * LDK + koff]; \
            af[mt][0] = lo.x; af[mt][1] = hi.x; af[mt][2] = lo.y; af[mt][3] = hi.y; \
        } \
        unsigned bf[8][2]; \
        _Pragma("unroll") \
        for (int nt = 0; nt < 8; ++nt) { \
            const uint2 bv = *(const uint2*)&usm[fB + nt * (8 * LDK) + koff]; \
            bf[nt][0] = bv.x; bf[nt][1] = bv.y; \
        } \
        _Pragma("unroll") \
        for (int mt = 0; mt < 4; ++mt) \
            _Pragma("unroll") \
            for (int nt = 0; nt < 8; ++nt) \
                mma_tf32(acc[mt][nt], af[mt], bf[nt]); \
    } \
} while (0)

__global__ __launch_bounds__(256)
void gemm_tf32f(const unsigned* __restrict__ A,
                const unsigned* __restrict__ W0, const unsigned* __restrict__ W1,
                const unsigned* __restrict__ W2,
                const float* __restrict__ b0, const float* __restrict__ b1,
                const float* __restrict__ b2,
                float* __restrict__ C0, float* __restrict__ C1, float* __restrict__ C2,
                float s0, float s1, float s2)
{
    extern __shared__ unsigned usm[];

    const int sel = blockIdx.x / 3;
    const int n0  = (blockIdx.x % 3) * BN4;
    const int m0  = blockIdx.y * BM4;
    const unsigned* W = (sel == 0) ? W0 : (sel == 1) ? W1 : W2;
    const float* bias = (sel == 0) ? b0 : (sel == 1) ? b1 : b2;
    float* C          = (sel == 0) ? C0 : (sel == 1) ? C1 : C2;
    const float scale = (sel == 0) ? s0 : (sel == 1) ? s1 : s2;

    const int tid = threadIdx.x;
    // loader mapping: kg = 4-float k-group, ra = row 0..63
    const int kg = tid & 3;
    const int ra = tid >> 2;
    const int kgl = kg & 1, kgh = kg >> 1;
    const unsigned sra = 2u * (((ra & 3) + 2 * ((ra >> 2) & 1)) & 3);
    const unsigned stA = (unsigned)(ra * LDK + kgl + 8 * kgh);
    unsigned jx[4];
    #pragma unroll
    for (int j = 0; j < 4; ++j) jx[j] = (unsigned)(2 * j) ^ sra;

    // compute mapping: 8 warps = 2(M) x 4(N), warp tile 64x64
    const int warp = tid >> 5, lane = tid & 31;
    const int g = lane >> 2, tig = lane & 3;
    const int wm = (warp & 1) * 64;
    const int wn = (warp >> 1) * 64;
    const unsigned sg = 2u * (((g & 3) + 2 * ((g >> 2) & 1)) & 3);
    const unsigned fA = (unsigned)((wm + g) * LDK) + (((unsigned)(2 * tig)) ^ sg);
    const unsigned fB = BOFF + (unsigned)((wn + g) * LDK) + (((unsigned)(2 * tig)) ^ sg);

    const unsigned* Ap0 = A + (size_t)(m0 + ra)       * EMB + kg * 4;
    const unsigned* Ap1 = A + (size_t)(m0 + ra + 64)  * EMB + kg * 4;
    const unsigned* Bp0 = W + (size_t)(n0 + ra)       * EMB + kg * 4;
    const unsigned* Bp1 = W + (size_t)(n0 + ra + 64)  * EMB + kg * 4;
    const unsigned* Bp2 = W + (size_t)(n0 + ra + 128) * EMB + kg * 4;
    const unsigned* Bp3 = W + (size_t)(n0 + ra + 192) * EMB + kg * 4;

    float acc[4][8][4];
    #pragma unroll
    for (int mt = 0; mt < 4; ++mt)
        #pragma unroll
        for (int nt = 0; nt < 8; ++nt)
            #pragma unroll
            for (int l = 0; l < 4; ++l) acc[mt][nt][l] = 0.f;

    // preload chunk 0 -> buf0
    {
        const uint4 a0 = *(const uint4*)(Ap0);
        const uint4 a1 = *(const uint4*)(Ap1);
        const uint4 w0 = *(const uint4*)(Bp0);
        const uint4 w1 = *(const uint4*)(Bp1);
        const uint4 w2 = *(const uint4*)(Bp2);
        const uint4 w3 = *(const uint4*)(Bp3);
        STORE6(0, a0, a1, w0, w1, w2, w3);
    }
    __syncthreads();

    #pragma unroll 1
    for (int t = 0; t < 48; t += 2) {
        // chunk t on buf0; prefetch chunk t+1 -> buf1
        const uint4 a0 = *(const uint4*)(Ap0 + 16);
        const uint4 a1 = *(const uint4*)(Ap1 + 16);
        const uint4 w0 = *(const uint4*)(Bp0 + 16);
        const uint4 w1 = *(const uint4*)(Bp1 + 16);
        const uint4 w2 = *(const uint4*)(Bp2 + 16);
        const uint4 w3 = *(const uint4*)(Bp3 + 16);
        GEMM_STEP(0);
        STORE6(16, a0, a1, w0, w1, w2, w3);
        __syncthreads();

        // chunk t+1 on buf1; prefetch chunk t+2 -> buf0
        const bool more = (t + 2 < 48);
        uint4 b0v, b1v, c0, c1, c2, c3;
        if (more) {
            b0v = *(const uint4*)(Ap0 + 32);
            b1v = *(const uint4*)(Ap1 + 32);
            c0  = *(const uint4*)(Bp0 + 32);
            c1  = *(const uint4*)(Bp1 + 32);
            c2  = *(const uint4*)(Bp2 + 32);
            c3  = *(const uint4*)(Bp3 + 32);
        }
        GEMM_STEP(16);
        if (more) STORE6(0, b0v, b1v, c0, c1, c2, c3);
        Ap0 += 32; Ap1 += 32; Bp0 += 32; Bp1 += 32; Bp2 += 32; Bp3 += 32;
        __syncthreads();
    }

    // ---- epilogue: C = (acc + bias) * scale ----
    #pragma unroll
    for (int mt = 0; mt < 4; ++mt) {
        const int rbase = m0 + wm + mt * 16 + g;
        #pragma unroll
        for (int nt = 0; nt < 8; ++nt) {
            const int cbase = n0 + wn + nt * 8 + tig * 2;
            const float bv0 = bias[cbase];
            const float bv1 = bias[cbase + 1];
            C[(size_t)rbase * EMB + cbase]           = (acc[mt][nt][0] + bv0) * scale;
            C[(size_t)rbase * EMB + cbase + 1]       = (acc[mt][nt][1] + bv1) * scale;
            C[(size_t)(rbase + 8) * EMB + cbase]     = (acc[mt][nt][2] + bv0) * scale;
            C[(size_t)(rbase + 8) * EMB + cbase + 1] = (acc[mt][nt][3] + bv1) * scale;
        }
    }
}

// ---------------- tensor-core axial attention v2 (unchanged from R15 pass) ----------------
#define ALD 72
#define QIDX(d, r) ((d)*ALD + ((r) ^ (((d) & 12) << 1)))
#define AH (3 * 64 * ALD)                 // per-head u32 block
#define ATT_SMEM (2 * AH * 4)             // 110592 bytes

__global__ __launch_bounds__(256)
void attn_tc2(const float* __restrict__ q, const float* __restrict__ k,
              const float* __restrict__ v, float* __restrict__ o, int axis)
{
    extern __shared__ unsigned asm_[];

    const int bid = blockIdx.x;
    const int n2 = bid % 6;               // head pair: heads 2*n2, 2*n2+1
    const int rem = bid / 6;
    const int outer = rem % NH;
    const int b = rem / NH;

    size_t tbase;
    long stride;
    if (axis == 0) {
        tbase = ((size_t)(b * NH + outer) * NW) * EMB;
        stride = EMB;
    } else {
        tbase = ((size_t)b * NH * NW + outer) * EMB;
        stride = (long)NW * EMB;
    }
    const size_t base0 = tbase + (size_t)(2 * n2) * HDIM;

    const int tid = threadIdx.x;
    #pragma unroll
    for (int hh = 0; hh < 2; ++hh) {
        unsigned* QTh = asm_ + hh * AH;
        unsigned* KTh = QTh + 64 * ALD;
        unsigned* VSh = KTh + 64 * ALD;
        const size_t hb = base0 + (size_t)hh * HDIM;
        for (int i = tid; i < NH * HDIM; i += 256) {
            const int r = i >> 6, d = i & 63;
            const size_t gaddr = hb + (size_t)r * stride + d;
            QTh[QIDX(d, r)] = f2tf(q[gaddr]);
            KTh[QIDX(d, r)] = f2tf(k[gaddr]);
            VSh[r * ALD + d] = f2tf(v[gaddr]);
        }
    }
    __syncthreads();

    const int warp = tid >> 5, lane = tid & 31;
    const int g8 = lane >> 2, tig = lane & 3;
    const int h = warp >> 2;              // head within CTA
    const int w4 = warp & 3;
    const int wm = (w4 & 1) * 32;         // 2 m-halves
    const int wn = (w4 >> 1) * 32;        // 2 n-halves

    unsigned* QT = asm_ + h * AH;
    unsigned* KT = QT + 64 * ALD;
    unsigned* VS = KT + 64 * ALD;
    float* Sf = (float*)KT;

    // ---- S = Q K^T (64x64x64, warp does 32x32) ----
    float acc[2][4][4];
    #pragma unroll
    for (int mt = 0; mt < 2; ++mt)
        #pragma unroll
        for (int nt = 0; nt < 4; ++nt)
            #pragma unroll
            for (int l = 0; l < 4; ++l) acc[mt][nt][l] = 0.f;

    #pragma unroll
    for (int kk = 0; kk < 64; kk += 8) {
        unsigned af[2][4];
        #pragma unroll
        for (int mt = 0; mt < 2; ++mt) {
            const int r = wm + mt * 16 + g8;
            af[mt][0] = QT[QIDX(kk + tig,     r)];
            af[mt][1] = QT[QIDX(kk + tig,     r + 8)];
            af[mt][2] = QT[QIDX(kk + tig + 4, r)];
            af[mt][3] = QT[QIDX(kk + tig + 4, r + 8)];
        }
        #pragma unroll
        for (int nt = 0; nt < 4; ++nt) {
            unsigned bf[2];
            const int c = wn + nt * 8 + g8;
            bf[0] = KT[QIDX(kk + tig,     c)];
            bf[1] = KT[QIDX(kk + tig + 4, c)];
            #pragma unroll
            for (int mt = 0; mt < 2; ++mt)
                mma_tf32(acc[mt][nt], af[mt], bf);
        }
    }
    __syncthreads();   // QT/KT reads done before overwriting KT with S

    #pragma unroll
    for (int mt = 0; mt < 2; ++mt) {
        const int r = wm + mt * 16 + g8;
        #pragma unroll
        for (int nt = 0; nt < 4; ++nt) {
            const int c = wn + nt * 8 + tig * 2;
            Sf[r * ALD + c]           = acc[mt][nt][0];
            Sf[r * ALD + c + 1]       = acc[mt][nt][1];
            Sf[(r + 8) * ALD + c]     = acc[mt][nt][2];
            Sf[(r + 8) * ALD + c + 1] = acc[mt][nt][3];
        }
    }
    __syncthreads();

    // ---- softmax rows -> P^T (tf32) into QT region (per head, 4 warps) ----
    for (int x = w4; x < NH; x += 4) {
        const float s0v = Sf[x * ALD + lane];
        const bool hi = (lane < NH - 32);
        const float s1v = hi ? Sf[x * ALD + lane + 32] : -1e30f;
        float m = fmaxf(s0v, s1v);
        #pragma unroll
        for (int off = 16; off; off >>= 1)
            m = fmaxf(m, __shfl_xor_sync(0xffffffffu, m, off));
        const float e0 = __expf(s0v - m);
        const float e1 = hi ? __expf(s1v - m) : 0.f;
        float sum = e0 + e1;
        #pragma unroll
        for (int off = 16; off; off >>= 1)
            sum += __shfl_xor_sync(0xffffffffu, sum, off);
        const float inv = __fdividef(1.f, sum);

        QT[QIDX(lane, x)] = f2tf(e0 * inv);
        if (hi) QT[QIDX(lane + 32, x)] = f2tf(e1 * inv);
    }
    __syncthreads();

    // ---- O = P V (K=56 -> 7 k8 steps) ----
    float oc[2][4][4];
    #pragma unroll
    for (int mt = 0; mt < 2; ++mt)
        #pragma unroll
        for (int nt = 0; nt < 4; ++nt)
            #pragma unroll
            for (int l = 0; l < 4; ++l) oc[mt][nt][l] = 0.f;

    #pragma unroll
    for (int kk = 0; kk < NH; kk += 8) {
        unsigned af[2][4];
        #pragma unroll
        for (int mt = 0; mt < 2; ++mt) {
            const int r = wm + mt * 16 + g8;
            af[mt][0] = QT[QIDX(kk + tig,     r)];
            af[mt][1] = QT[QIDX(kk + tig,     r + 8)];
            af[mt][2] = QT[QIDX(kk + tig + 4, r)];
            af[mt][3] = QT[QIDX(kk + tig + 4, r + 8)];
        }
        #pragma unroll
        for (int nt = 0; nt < 4; ++nt) {
            unsigned bf[2];
            const int c = wn + nt * 8 + g8;
            bf[0] = VS[(kk + tig    ) * ALD + c];
            bf[1] = VS[(kk + tig + 4) * ALD + c];
            #pragma unroll
            for (int mt = 0; mt < 2; ++mt)
                mma_tf32(oc[mt][nt], af[mt], bf);
        }
    }

    const size_t obase = base0 + (size_t)h * HDIM;
    #pragma unroll
    for (int mt = 0; mt < 2; ++mt) {
        const int r0 = wm + mt * 16 + g8, r1 = r0 + 8;
        #pragma unroll
        for (int nt = 0; nt < 4; ++nt) {
            const int c = wn + nt * 8 + tig * 2;
            if (r0 < NH) {
                o[obase + (size_t)r0 * stride + c]     = oc[mt][nt][0];
                o[obase + (size_t)r0 * stride + c + 1] = oc[mt][nt][1];
            }
            if (r1 < NH) {
                o[obase + (size_t)r1 * stride + c]     = oc[mt][nt][2];
                o[obase + (size_t)r1 * stride + c + 1] = oc[mt][nt][3];
            }
        }
    }
}

// ---------------- launch ----------------
extern "C" void kernel_launch(void* const* d_in, const int* in_sizes, int n_in,
                              void* d_out, int out_size)
{
    (void)in_sizes; (void)n_in; (void)out_size;
    const float* x  = (const float*)d_in[0];
    const float* Wq = (const float*)d_in[1];
    const float* bq = (const float*)d_in[2];
    const float* Wk = (const float*)d_in[3];
    const float* bk = (const float*)d_in[4];
    const float* Wv = (const float*)d_in[5];
    const float* bv = (const float*)d_in[6];
    const float* Wo = (const float*)d_in[7];
    const float* bo = (const float*)d_in[8];
    float* out = (float*)d_out;

    float *qp, *kp, *vp;
    unsigned *xt, *wt;
    cudaGetSymbolAddress((void**)&qp, g_q);
    cudaGetSymbolAddress((void**)&kp, g_k);
    cudaGetSymbolAddress((void**)&vp, g_v);
    cudaGetSymbolAddress((void**)&xt, g_xt);
    cudaGetSymbolAddress((void**)&wt, g_wt);

    cudaFuncSetAttribute(gemm_tf32f, cudaFuncAttributeMaxDynamicSharedMemorySize, GEMM_SMEM);
    cudaFuncSetAttribute(attn_tc2, cudaFuncAttributeMaxDynamicSharedMemorySize, ATT_SMEM);

    const int nx4 = NTOK * EMB / 4;
    const int nw4 = WSZ / 4;

    // pre-convert operands to tf32 (once)
    conv_tf32<<<(nx4 + 255) / 256, 256>>>(x, xt, nx4);
    conv_tf32<<<(nw4 + 255) / 256, 256>>>(Wq, wt + 0 * WSZ, nw4);
    conv_tf32<<<(nw4 + 255) / 256, 256>>>(Wk, wt + 1 * WSZ, nw4);
    conv_tf32<<<(nw4 + 255) / 256, 256>>>(Wv, wt + 2 * WSZ, nw4);
    conv_tf32<<<(nw4 + 255) / 256, 256>>>(Wo, wt + 3 * WSZ, nw4);

    // fused QKV projections (K pre-scaled by 1/sqrt(d))
    gemm_tf32f<<<dim3(9, NTOK / BM4), 256, GEMM_SMEM>>>(
        xt, wt, wt + WSZ, wt + 2 * WSZ, bq, bk, bv, qp, kp, vp, 1.0f, SCALING, 1.0f);

    // width attention: vw overwrites V ; height attention: overwrites Q
    attn_tc2<<<NB * NH * 6, 256, ATT_SMEM>>>(qp, kp, vp, vp, 0);
    attn_tc2<<<NB * NW * 6, 256, ATT_SMEM>>>(qp, kp, vp, qp, 1);

    // convert attention output, then output projection
    conv_tf32<<<(nx4 + 255) / 256, 256>>>(qp, xt, nx4);
    gemm_tf32f<<<dim3(3, NTOK / BM4), 256, GEMM_SMEM>>>(
        xt, wt + 3 * WSZ, wt + 3 * WSZ, wt + 3 * WSZ, bo, bo, bo,
        out, out, out, 1.0f, 1.0f, 1.0f);
}